// round 3
// baseline (speedup 1.0000x reference)
#include <cuda_runtime.h>

// Loss_60567628808292: YOLO loss (bugs faithfully reproduced), fully fused.
// pred, target: [batch, 7, 7, 30] float32; M = batch*49 rows of 30 floats.
// out: scalar float32 = bbox_loss + noobj_loss.
//
// Layout fact: needed channels (4,9) touch EVERY 128B line of both tensors,
// so full-array streaming is the traffic floor. This version streams both
// tensors with coalesced float4 loads and extracts ch4/ch9 via smem.

#define NCH 30
#define SDIM 7.0f
#define L_COORD 5.0f
#define L_NOOBJ 0.5f
#define MAX_ACTIVE 49   /* S*S */
#define THREADS 256
#define TILE_ROWS 512                      /* rows per noobj tile   */
#define TILE_F4  (TILE_ROWS * NCH / 4)     /* 3840 float4 per tensor */
#define ITERS    (TILE_F4 / THREADS)       /* 15 */

// Cross-block accumulator + completion counter. Zero at load; last block
// publishes out[] and resets both -> deterministic across graph replays.
__device__ float g_acc;
__device__ unsigned int g_done;

// ---------------------------------------------------------------------------
// Per-box "tot" value (l1+l2+l3+iou), reproducing the reference's buggy
// transform: x1 = x/7 - w/2 ; x2 = x1/7 + w/2 (uses the NEW xy).
// ---------------------------------------------------------------------------
__device__ __forceinline__ float box_tot(const float* __restrict__ pb,
                                         const float* __restrict__ tb,
                                         float& iou) {
    const float inv7 = 1.0f / SDIM;

    const float px = pb[0], py = pb[1], pw = pb[2], ph = pb[3], pc = pb[4];
    const float tx = tb[0], ty = tb[1], tw = tb[2], th = tb[3], tc = tb[4];

    const float px1 = px * inv7 - 0.5f * pw;
    const float py1 = py * inv7 - 0.5f * ph;
    const float px2 = px1 * inv7 + 0.5f * pw;   // original bug
    const float py2 = py1 * inv7 + 0.5f * ph;

    const float tx1 = tx * inv7 - 0.5f * tw;
    const float ty1 = ty * inv7 - 0.5f * th;
    const float tx2 = tx1 * inv7 + 0.5f * tw;
    const float ty2 = ty1 * inv7 + 0.5f * th;

    const float dx1 = tx1 - px1, dy1 = ty1 - py1;
    const float l1 = L_COORD * dx1 * dx1 + dy1 * dy1;   // lambda only on x (bug)

    const float sx = sqrtf(tx2) - sqrtf(px2);
    const float sy = sqrtf(ty2) - sqrtf(py2);
    const float l2 = L_COORD * sx * sx + sy * sy;       // lambda only on x (bug)

    const float dc = tc - pc;
    const float l3 = dc * dc;

    const float ltx = fmaxf(px1, tx1), lty = fmaxf(py1, ty1);
    const float rbx = fminf(px2, tx2), rby = fminf(py2, ty2);
    const float wx = fmaxf(rbx - ltx, 0.0f);
    const float wy = fmaxf(rby - lty, 0.0f);
    const float inter = wx * wy;
    const float ap = (px2 - px1) * (py2 - py1);
    const float at = (tx2 - tx1) * (ty2 - ty1);
    iou = inter / (ap + at - inter);

    return l1 + l2 + l3 + iou;   // IoU added into the selected loss (bug)
}

// ---------------------------------------------------------------------------
// Fused kernel.
//   block 0        : bbox loss (first MAX_ACTIVE obj rows in flatten order)
//   block b (>=1)  : noobj loss over tile b-1 (TILE_ROWS rows), streamed.
// ---------------------------------------------------------------------------
__global__ void __launch_bounds__(THREADS)
yolo_loss_kernel(const float* __restrict__ pred,
                 const float* __restrict__ tgt,
                 int M, float* __restrict__ out) {
    const int tid = threadIdx.x;
    const int lane = tid & 31;
    const int w = tid >> 5;
    float partial = 0.0f;   // valid on tid==0 at the end

    if (blockIdx.x == 0) {
        // ---------------- bbox scan ----------------
        __shared__ float s_acc;
        __shared__ int s_count;
        __shared__ int s_warp_cnt[THREADS / 32];
        const int nwarps = THREADS / 32;

        if (tid == 0) { s_acc = 0.0f; s_count = 0; }
        __syncthreads();

        for (int base = 0; base < M; base += THREADS) {
            const int r = base + tid;
            bool obj = false;
            if (r < M) obj = tgt[(size_t)r * NCH + 4] > 0.0f;

            const unsigned mask = __ballot_sync(0xffffffffu, obj);
            if (lane == 0) s_warp_cnt[w] = __popc(mask);
            __syncthreads();

            int before = 0, total = 0;
            #pragma unroll
            for (int j = 0; j < nwarps; j++) {
                const int c = s_warp_cnt[j];
                if (j < w) before += c;
                total += c;
            }
            const int rank = s_count + before + __popc(mask & ((1u << lane) - 1u));

            if (obj && rank < MAX_ACTIVE) {
                const float* p = pred + (size_t)r * NCH;
                const float* t = tgt + (size_t)r * NCH;
                float iou0, iou1;
                const float tot0 = box_tot(p,     t,     iou0);
                const float tot1 = box_tot(p + 5, t + 5, iou1);
                const float sel = (iou1 > iou0) ? tot1 : tot0;  // argmax: first wins ties
                atomicAdd(&s_acc, sel);
            }
            __syncthreads();
            if (tid == 0) s_count += total;
            __syncthreads();
            if (s_count >= MAX_ACTIVE) break;
        }
        if (tid == 0) partial = s_acc;
    } else {
        // ---------------- noobj streaming tile ----------------
        // Fully-coalesced float4 streaming of pred & tgt. For float4 at
        // float-index fl (fl % 30 even): b==4 -> lane0 is ch4 (even row),
        // b==2 -> lane2 is ch4 (odd row), b==8 -> lane1 is ch9 (even row),
        // b==6 -> lane3 is ch9 (odd row). Each row's ch4/ch9 appear exactly
        // once; the final 2-float remainder (when M odd) is ch28/29 -> unused.
        __shared__ float t4s[TILE_ROWS];
        __shared__ float p4s[TILE_ROWS];
        __shared__ float d9s[TILE_ROWS];

        const int tile = blockIdx.x - 1;
        const int rowS = tile * TILE_ROWS;
        const int nf4 = (M * NCH) >> 2;          // floor; covers all ch4/ch9
        const float4* __restrict__ pred4 = (const float4*)pred;
        const float4* __restrict__ tgt4 = (const float4*)tgt;

        int i4 = tile * TILE_F4 + tid;
        int fl = i4 << 2;
        int q = fl / NCH;                        // row of this float4's base
        int b = fl - q * NCH;                    // fl % 30 (even)

        #pragma unroll
        for (int k = 0; k < ITERS; k++) {
            if (i4 < nf4) {
                const float4 P = __ldg(pred4 + i4);
                const float4 T = __ldg(tgt4 + i4);
                if (b == 4) {            // ch4, even row, lane 0
                    t4s[q - rowS] = T.x; p4s[q - rowS] = P.x;
                } else if (b == 2) {     // ch4, odd row, lane 2
                    t4s[q - rowS] = T.z; p4s[q - rowS] = P.z;
                } else if (b == 8) {     // ch9, even row, lane 1
                    const float d = P.y - T.y; d9s[q - rowS] = d * d;
                } else if (b == 6) {     // ch9, odd row, lane 3
                    const float d = P.w - T.w; d9s[q - rowS] = d * d;
                }
            }
            // advance by 256 float4 = 1024 floats = 34*30 + 4
            i4 += THREADS;
            b += 4; q += 34;
            if (b >= NCH) { b -= NCH; q += 1; }
        }
        __syncthreads();

        // compute phase: 2 rows per thread
        const int nrows = min(TILE_ROWS, M - rowS);
        float acc = 0.0f;
        for (int rr = tid; rr < nrows; rr += THREADS) {
            const float t4 = t4s[rr];
            if (!(t4 > 0.0f)) {
                const float d0 = p4s[rr] - t4;
                acc += d0 * d0 + d9s[rr];
            }
        }
        acc *= L_NOOBJ;

        // warp + block reduce
        #pragma unroll
        for (int off = 16; off > 0; off >>= 1)
            acc += __shfl_xor_sync(0xffffffffu, acc, off);

        __shared__ float warp_sums[THREADS / 32];
        if (lane == 0) warp_sums[w] = acc;
        __syncthreads();
        if (w == 0) {
            float v = (lane < THREADS / 32) ? warp_sums[lane] : 0.0f;
            #pragma unroll
            for (int off = 16; off > 0; off >>= 1)
                v += __shfl_xor_sync(0xffffffffu, v, off);
            if (lane == 0) partial = v;
        }
    }

    // ---------------- completion protocol ----------------
    if (tid == 0) {
        atomicAdd(&g_acc, partial);
        __threadfence();
        const unsigned old = atomicAdd(&g_done, 1u);
        if (old == gridDim.x - 1) {
            out[0] = atomicExch(&g_acc, 0.0f);
            atomicExch(&g_done, 0u);
        }
    }
}

// ---------------------------------------------------------------------------
extern "C" void kernel_launch(void* const* d_in, const int* in_sizes, int n_in,
                              void* d_out, int out_size) {
    const float* pred = (const float*)d_in[0];
    const float* tgt  = (const float*)d_in[1];
    float* out = (float*)d_out;

    const int M = in_sizes[0] / NCH;

    int ntiles = (M + TILE_ROWS - 1) / TILE_ROWS;
    if (ntiles < 1) ntiles = 1;
    yolo_loss_kernel<<<ntiles + 1, THREADS>>>(pred, tgt, M, out);
}

// round 4
// speedup vs baseline: 1.3704x; 1.3704x over previous
#include <cuda_runtime.h>

// Loss_60567628808292: YOLO loss (bugs faithfully reproduced), fully fused.
// pred, target: [batch, 7, 7, 30] float32; M = batch*49 rows of 30 floats.
// out: scalar float32 = bbox_loss + noobj_loss.
//
// Channels (4,9) touch every 128B line of both tensors -> full-array
// streaming is the traffic floor (196 MB). This version streams both tensors
// with coalesced float4 loads and a branch-free one-shuffle extraction:
// for every row, ch4's float4 index is exactly ch9's index - 1.

#define NCH 30
#define SDIM 7.0f
#define L_COORD 5.0f
#define L_NOOBJ 0.5f
#define MAX_ACTIVE 49   /* S*S */
#define THREADS 256
#define ITERS 16
#define CHUNK_F4 (THREADS * ITERS)   /* 4096 float4 per tensor per block */

// Cross-block accumulator + completion counter. Zero at load; last block
// publishes out[] and resets both -> same initial state every graph replay.
__device__ float g_acc;
__device__ unsigned int g_done;

// ---------------------------------------------------------------------------
// Per-box "tot" value (l1+l2+l3+iou), reproducing the reference's buggy
// transform: x1 = x/7 - w/2 ; x2 = x1/7 + w/2 (uses the NEW xy).
// ---------------------------------------------------------------------------
__device__ __forceinline__ float box_tot(const float* __restrict__ pb,
                                         const float* __restrict__ tb,
                                         float& iou) {
    const float inv7 = 1.0f / SDIM;

    const float px = pb[0], py = pb[1], pw = pb[2], ph = pb[3], pc = pb[4];
    const float tx = tb[0], ty = tb[1], tw = tb[2], th = tb[3], tc = tb[4];

    const float px1 = px * inv7 - 0.5f * pw;
    const float py1 = py * inv7 - 0.5f * ph;
    const float px2 = px1 * inv7 + 0.5f * pw;   // original bug
    const float py2 = py1 * inv7 + 0.5f * ph;

    const float tx1 = tx * inv7 - 0.5f * tw;
    const float ty1 = ty * inv7 - 0.5f * th;
    const float tx2 = tx1 * inv7 + 0.5f * tw;
    const float ty2 = ty1 * inv7 + 0.5f * th;

    const float dx1 = tx1 - px1, dy1 = ty1 - py1;
    const float l1 = L_COORD * dx1 * dx1 + dy1 * dy1;   // lambda only on x (bug)

    const float sx = sqrtf(tx2) - sqrtf(px2);
    const float sy = sqrtf(ty2) - sqrtf(py2);
    const float l2 = L_COORD * sx * sx + sy * sy;       // lambda only on x (bug)

    const float dc = tc - pc;
    const float l3 = dc * dc;

    const float ltx = fmaxf(px1, tx1), lty = fmaxf(py1, ty1);
    const float rbx = fminf(px2, tx2), rby = fminf(py2, ty2);
    const float wx = fmaxf(rbx - ltx, 0.0f);
    const float wy = fmaxf(rby - lty, 0.0f);
    const float inter = wx * wy;
    const float ap = (px2 - px1) * (py2 - py1);
    const float at = (tx2 - tx1) * (ty2 - ty1);
    iou = inter / (ap + at - inter);

    return l1 + l2 + l3 + iou;   // IoU added into the selected loss (bug)
}

// ---------------------------------------------------------------------------
// Fused kernel.
//   block 0        : bbox loss (first MAX_ACTIVE obj rows in flatten order)
//   block b (>=1)  : noobj loss over chunk b-1 of the float4 index space.
// ---------------------------------------------------------------------------
__global__ void __launch_bounds__(THREADS)
yolo_loss_kernel(const float* __restrict__ pred,
                 const float* __restrict__ tgt,
                 int M, float* __restrict__ out) {
    const int tid = threadIdx.x;
    const int lane = tid & 31;
    const int w = tid >> 5;
    float partial = 0.0f;   // valid on tid==0 at the end

    if (blockIdx.x == 0) {
        // ---------------- bbox scan ----------------
        __shared__ float s_acc;
        __shared__ int s_count;
        __shared__ int s_warp_cnt[THREADS / 32];
        const int nwarps = THREADS / 32;

        if (tid == 0) { s_acc = 0.0f; s_count = 0; }
        __syncthreads();

        for (int base = 0; base < M; base += THREADS) {
            const int r = base + tid;
            bool obj = false;
            if (r < M) obj = tgt[(size_t)r * NCH + 4] > 0.0f;

            const unsigned mask = __ballot_sync(0xffffffffu, obj);
            if (lane == 0) s_warp_cnt[w] = __popc(mask);
            __syncthreads();

            int before = 0, total = 0;
            #pragma unroll
            for (int j = 0; j < nwarps; j++) {
                const int c = s_warp_cnt[j];
                if (j < w) before += c;
                total += c;
            }
            const int rank = s_count + before + __popc(mask & ((1u << lane) - 1u));

            if (obj && rank < MAX_ACTIVE) {
                const float* p = pred + (size_t)r * NCH;
                const float* t = tgt + (size_t)r * NCH;
                float iou0, iou1;
                const float tot0 = box_tot(p,     t,     iou0);
                const float tot1 = box_tot(p + 5, t + 5, iou1);
                const float sel = (iou1 > iou0) ? tot1 : tot0;  // argmax: first wins ties
                atomicAdd(&s_acc, sel);
            }
            __syncthreads();
            if (tid == 0) s_count += total;
            __syncthreads();
            if (s_count >= MAX_ACTIVE) break;
        }
        if (tid == 0) partial = s_acc;
    } else {
        // ---------------- noobj streaming chunk ----------------
        // Thread t handles float4 indices i4 = chunk*CHUNK_F4 + t + k*THREADS.
        // b = (4*i4) mod 30 (even). b==4 -> T.x/P.x is this row's ch4;
        // b==2 -> T.z/P.z. b==8 -> P.y-T.y is this row's d9; b==6 -> P.w-T.w.
        // The ch4-holding float4 index is always (ch9-holding index) - 1, so
        // one shfl_up(1) pairs them. Message v = (t4>0) ? -1 : (p4-t4)^2.
        const int nf4 = (M * NCH) >> 2;   // remainder floats are ch28/29 only
        const float4* __restrict__ pred4 = (const float4*)pred;
        const float4* __restrict__ tgt4 = (const float4*)tgt;

        int i4 = (blockIdx.x - 1) * CHUNK_F4 + tid;
        int b = (i4 << 2) % NCH;
        float acc = 0.0f;

        #pragma unroll
        for (int k = 0; k < ITERS; k++) {
            const bool active = (i4 < nf4);
            float4 P = make_float4(0.f, 0.f, 0.f, 0.f);
            float4 T = make_float4(1.f, 1.f, 1.f, 1.f);  // t>0 -> v=-1 (inert)
            if (active) { P = __ldg(pred4 + i4); T = __ldg(tgt4 + i4); }

            // sender side (b in {2,4}); harmless garbage otherwise
            const bool b4 = (b == 4);
            const float tg = b4 ? T.x : T.z;
            const float pg = b4 ? P.x : P.z;
            const float dg = pg - tg;
            const float v = (tg > 0.0f) ? -1.0f : dg * dg;

            const float vu = __shfl_up_sync(0xffffffffu, v, 1);

            // receiver side (b in {6,8})
            const bool b8 = (b == 8);
            if (active & (b8 | (b == 6))) {
                const float d9 = b8 ? (P.y - T.y) : (P.w - T.w);
                float vv = vu;
                if (lane == 0) {   // pair lives in the previous warp's float4
                    const int idx = (i4 << 2) - (b8 ? 4 : 2);
                    const float t4 = __ldg(tgt + idx);
                    const float p4 = __ldg(pred + idx);
                    const float d = p4 - t4;
                    vv = (t4 > 0.0f) ? -1.0f : d * d;
                }
                if (vv >= 0.0f) acc += vv + d9 * d9;
            }

            i4 += THREADS;
            b += 4;                       // 1024 floats == 4 (mod 30)
            if (b >= NCH) b -= NCH;
        }
        acc *= L_NOOBJ;

        // warp + block reduce
        #pragma unroll
        for (int off = 16; off > 0; off >>= 1)
            acc += __shfl_xor_sync(0xffffffffu, acc, off);

        __shared__ float warp_sums[THREADS / 32];
        if (lane == 0) warp_sums[w] = acc;
        __syncthreads();
        if (w == 0) {
            float vv = (lane < THREADS / 32) ? warp_sums[lane] : 0.0f;
            #pragma unroll
            for (int off = 16; off > 0; off >>= 1)
                vv += __shfl_xor_sync(0xffffffffu, vv, off);
            if (lane == 0) partial = vv;
        }
    }

    // ---------------- completion protocol ----------------
    if (tid == 0) {
        atomicAdd(&g_acc, partial);
        __threadfence();
        const unsigned old = atomicAdd(&g_done, 1u);
        if (old == gridDim.x - 1) {
            out[0] = atomicExch(&g_acc, 0.0f);
            atomicExch(&g_done, 0u);
        }
    }
}

// ---------------------------------------------------------------------------
extern "C" void kernel_launch(void* const* d_in, const int* in_sizes, int n_in,
                              void* d_out, int out_size) {
    const float* pred = (const float*)d_in[0];
    const float* tgt  = (const float*)d_in[1];
    float* out = (float*)d_out;

    const int M = in_sizes[0] / NCH;
    const int nf4 = (M * NCH) >> 2;

    int nchunks = (nf4 + CHUNK_F4 - 1) / CHUNK_F4;
    if (nchunks < 1) nchunks = 1;
    yolo_loss_kernel<<<nchunks + 1, THREADS>>>(pred, tgt, M, out);
}

// round 5
// speedup vs baseline: 1.4456x; 1.0548x over previous
#include <cuda_runtime.h>
#include <cstdint>

// Loss_60567628808292: YOLO loss (bugs faithfully reproduced), fully fused.
// pred, target: [batch, 7, 7, 30] float32; M = batch*49 rows of 30 floats.
// out: scalar float32 = bbox_loss + noobj_loss.
//
// All 128B lines of both tensors are touched (needed channels repeat every
// 120B), so full-array streaming (~196 MB) is the traffic floor. This
// version streams via cp.async.bulk (TMA) into smem tiles with a 2-stage
// mbarrier pipeline -> near-zero issue cost on the load path.

#define NCH 30
#define SDIM 7.0f
#define L_COORD 5.0f
#define L_NOOBJ 0.5f
#define MAX_ACTIVE 49   /* S*S */
#define THREADS 256

#define TILE_ROWS 200
#define TILE_BYTES (TILE_ROWS * NCH * 4)   /* 24000 B per tensor   */
#define STAGE_BYTES (2 * TILE_BYTES)       /* 48000 B (pred+tgt)   */
#define NSTAGES 2
#define DYN_SMEM (NSTAGES * STAGE_BYTES)   /* 96000 B              */
#define NOOBJ_BLOCKS 304                   /* 2 per SM x 152 SMs   */

// Cross-block accumulator + completion counter. Zero at load; last block
// publishes out[] and resets both -> same initial state every graph replay.
__device__ float g_acc;
__device__ unsigned int g_done;

// ---------------------------------------------------------------------------
static __device__ __forceinline__ uint32_t smem_u32(const void* p) {
    uint32_t a;
    asm("{ .reg .u64 t; cvta.to.shared.u64 t, %1; cvt.u32.u64 %0, t; }"
        : "=r"(a) : "l"(p));
    return a;
}

static __device__ __forceinline__ void mbar_init(uint32_t mbar, uint32_t cnt) {
    asm volatile("mbarrier.init.shared.b64 [%0], %1;" :: "r"(mbar), "r"(cnt) : "memory");
}

static __device__ __forceinline__ void mbar_expect_tx(uint32_t mbar, uint32_t bytes) {
    asm volatile("mbarrier.arrive.expect_tx.shared.b64 _, [%0], %1;"
                 :: "r"(mbar), "r"(bytes) : "memory");
}

static __device__ __forceinline__ void bulk_g2s(uint32_t dst, const void* src,
                                                uint32_t bytes, uint32_t mbar) {
    asm volatile(
        "cp.async.bulk.shared::cluster.global.mbarrier::complete_tx::bytes "
        "[%0], [%1], %2, [%3];"
        :: "r"(dst), "l"(src), "r"(bytes), "r"(mbar) : "memory");
}

static __device__ __forceinline__ void mbar_wait(uint32_t mbar, uint32_t parity) {
    asm volatile(
        "{\n\t"
        ".reg .pred P;\n\t"
        "WAIT_%=:\n\t"
        "mbarrier.try_wait.parity.acquire.cta.shared::cta.b64 P, [%0], %1, 0x989680;\n\t"
        "@P bra DONE_%=;\n\t"
        "bra WAIT_%=;\n\t"
        "DONE_%=:\n\t"
        "}"
        :: "r"(mbar), "r"(parity) : "memory");
}

// ---------------------------------------------------------------------------
// Per-box "tot" value (l1+l2+l3+iou), reproducing the reference's buggy
// transform: x1 = x/7 - w/2 ; x2 = x1/7 + w/2 (uses the NEW xy).
// ---------------------------------------------------------------------------
__device__ __forceinline__ float box_tot(const float* __restrict__ pb,
                                         const float* __restrict__ tb,
                                         float& iou) {
    const float inv7 = 1.0f / SDIM;

    const float px = pb[0], py = pb[1], pw = pb[2], ph = pb[3], pc = pb[4];
    const float tx = tb[0], ty = tb[1], tw = tb[2], th = tb[3], tc = tb[4];

    const float px1 = px * inv7 - 0.5f * pw;
    const float py1 = py * inv7 - 0.5f * ph;
    const float px2 = px1 * inv7 + 0.5f * pw;   // original bug
    const float py2 = py1 * inv7 + 0.5f * ph;

    const float tx1 = tx * inv7 - 0.5f * tw;
    const float ty1 = ty * inv7 - 0.5f * th;
    const float tx2 = tx1 * inv7 + 0.5f * tw;
    const float ty2 = ty1 * inv7 + 0.5f * th;

    const float dx1 = tx1 - px1, dy1 = ty1 - py1;
    const float l1 = L_COORD * dx1 * dx1 + dy1 * dy1;   // lambda only on x (bug)

    const float sx = sqrtf(tx2) - sqrtf(px2);
    const float sy = sqrtf(ty2) - sqrtf(py2);
    const float l2 = L_COORD * sx * sx + sy * sy;       // lambda only on x (bug)

    const float dc = tc - pc;
    const float l3 = dc * dc;

    const float ltx = fmaxf(px1, tx1), lty = fmaxf(py1, ty1);
    const float rbx = fminf(px2, tx2), rby = fminf(py2, ty2);
    const float wx = fmaxf(rbx - ltx, 0.0f);
    const float wy = fmaxf(rby - lty, 0.0f);
    const float inter = wx * wy;
    const float ap = (px2 - px1) * (py2 - py1);
    const float at = (tx2 - tx1) * (ty2 - ty1);
    iou = inter / (ap + at - inter);

    return l1 + l2 + l3 + iou;   // IoU added into the selected loss (bug)
}

// ---------------------------------------------------------------------------
// Fused kernel.
//   block 0        : bbox loss (first MAX_ACTIVE obj rows in flatten order)
//   blocks >= 1    : noobj loss, TMA-staged 200-row tiles, 2-stage pipeline.
// ---------------------------------------------------------------------------
__global__ void __launch_bounds__(THREADS)
yolo_loss_kernel(const float* __restrict__ pred,
                 const float* __restrict__ tgt,
                 int M, float* __restrict__ out) {
    extern __shared__ float dyn[];   // NSTAGES x [pred tile | tgt tile]
    __shared__ uint64_t mbar_store[NSTAGES];

    const int tid = threadIdx.x;
    const int lane = tid & 31;
    const int w = tid >> 5;
    float partial = 0.0f;   // valid on tid==0 at the end

    if (blockIdx.x == 0) {
        // ---------------- bbox scan ----------------
        __shared__ float s_acc;
        __shared__ int s_count;
        __shared__ int s_warp_cnt[THREADS / 32];
        const int nwarps = THREADS / 32;

        if (tid == 0) { s_acc = 0.0f; s_count = 0; }
        __syncthreads();

        for (int base = 0; base < M; base += THREADS) {
            const int r = base + tid;
            bool obj = false;
            if (r < M) obj = tgt[(size_t)r * NCH + 4] > 0.0f;

            const unsigned mask = __ballot_sync(0xffffffffu, obj);
            if (lane == 0) s_warp_cnt[w] = __popc(mask);
            __syncthreads();

            int before = 0, total = 0;
            #pragma unroll
            for (int j = 0; j < nwarps; j++) {
                const int c = s_warp_cnt[j];
                if (j < w) before += c;
                total += c;
            }
            const int rank = s_count + before + __popc(mask & ((1u << lane) - 1u));

            if (obj && rank < MAX_ACTIVE) {
                const float* p = pred + (size_t)r * NCH;
                const float* t = tgt + (size_t)r * NCH;
                float iou0, iou1;
                const float tot0 = box_tot(p,     t,     iou0);
                const float tot1 = box_tot(p + 5, t + 5, iou1);
                const float sel = (iou1 > iou0) ? tot1 : tot0;  // argmax: first wins ties
                atomicAdd(&s_acc, sel);
            }
            __syncthreads();
            if (tid == 0) s_count += total;
            __syncthreads();
            if (s_count >= MAX_ACTIVE) break;
        }
        if (tid == 0) partial = s_acc;
    } else {
        // ---------------- noobj TMA-staged streaming ----------------
        const int nb = gridDim.x - 1;
        const int nt = (M + TILE_ROWS - 1) / TILE_ROWS;
        const uint32_t mbar0 = smem_u32(&mbar_store[0]);
        const uint32_t smem_base = smem_u32(dyn);

        if (tid == 0) {
            mbar_init(mbar0, 1);
            mbar_init(mbar0 + 8, 1);
        }
        __syncthreads();

        // issue tile into stage s (tid 0 only)
        auto issue = [&](int t, int s) {
            const int rows = min(TILE_ROWS, M - t * TILE_ROWS);
            const int rowsT = rows & ~1;                   // even rows -> 16B mult
            const uint32_t bytes = (uint32_t)rowsT * NCH * 4;
            const uint32_t mb = mbar0 + 8u * s;
            const uint32_t dst = smem_base + (uint32_t)s * STAGE_BYTES;
            mbar_expect_tx(mb, 2 * bytes);
            bulk_g2s(dst,              pred + (size_t)t * TILE_ROWS * NCH, bytes, mb);
            bulk_g2s(dst + TILE_BYTES, tgt  + (size_t)t * TILE_ROWS * NCH, bytes, mb);
        };

        int myTile = blockIdx.x - 1;
        if (myTile < nt && tid == 0) issue(myTile, 0);

        int par0 = 0, par1 = 0;
        float acc = 0.0f;
        int it = 0;
        for (; myTile < nt; myTile += nb, ++it) {
            const int s = it & 1;
            const int nxt = myTile + nb;
            if (nxt < nt && tid == 0) issue(nxt, s ^ 1);   // stage s^1 freed last iter

            if (s == 0) { mbar_wait(mbar0, par0);     par0 ^= 1; }
            else        { mbar_wait(mbar0 + 8, par1); par1 ^= 1; }

            const int rows = min(TILE_ROWS, M - myTile * TILE_ROWS);
            const int rowsT = rows & ~1;
            const float* Ps = dyn + (size_t)s * (STAGE_BYTES / 4);
            const float* Ts = Ps + (TILE_BYTES / 4);

            if (tid < rowsT) {
                const int o = tid * NCH;
                const float t4 = Ts[o + 4];
                const float t9 = Ts[o + 9];
                const float p4 = Ps[o + 4];
                const float p9 = Ps[o + 9];
                if (!(t4 > 0.0f)) {
                    const float d0 = p4 - t4;
                    const float d1 = p9 - t9;
                    acc += d0 * d0 + d1 * d1;
                }
            }
            if ((rows & 1) && tid == 0) {                  // rare odd tail row
                const size_t r = (size_t)myTile * TILE_ROWS + rowsT;
                const float t4 = __ldg(tgt + r * NCH + 4);
                if (!(t4 > 0.0f)) {
                    const float d0 = __ldg(pred + r * NCH + 4) - t4;
                    const float d1 = __ldg(pred + r * NCH + 9) - __ldg(tgt + r * NCH + 9);
                    acc += d0 * d0 + d1 * d1;
                }
            }
            __syncthreads();   // all done with stage s before it is refilled
        }
        acc *= L_NOOBJ;

        // warp + block reduce
        #pragma unroll
        for (int off = 16; off > 0; off >>= 1)
            acc += __shfl_xor_sync(0xffffffffu, acc, off);

        __shared__ float warp_sums[THREADS / 32];
        if (lane == 0) warp_sums[w] = acc;
        __syncthreads();
        if (w == 0) {
            float v = (lane < THREADS / 32) ? warp_sums[lane] : 0.0f;
            #pragma unroll
            for (int off = 16; off > 0; off >>= 1)
                v += __shfl_xor_sync(0xffffffffu, v, off);
            if (lane == 0) partial = v;
        }
    }

    // ---------------- completion protocol ----------------
    if (tid == 0) {
        atomicAdd(&g_acc, partial);
        __threadfence();
        const unsigned old = atomicAdd(&g_done, 1u);
        if (old == gridDim.x - 1) {
            out[0] = atomicExch(&g_acc, 0.0f);
            atomicExch(&g_done, 0u);
        }
    }
}

// ---------------------------------------------------------------------------
extern "C" void kernel_launch(void* const* d_in, const int* in_sizes, int n_in,
                              void* d_out, int out_size) {
    const float* pred = (const float*)d_in[0];
    const float* tgt  = (const float*)d_in[1];
    float* out = (float*)d_out;

    const int M = in_sizes[0] / NCH;

    cudaFuncSetAttribute(yolo_loss_kernel,
                         cudaFuncAttributeMaxDynamicSharedMemorySize, DYN_SMEM);

    const int nt = (M + TILE_ROWS - 1) / TILE_ROWS;
    int nb = NOOBJ_BLOCKS;
    if (nb > nt) nb = nt;
    if (nb < 1) nb = 1;
    yolo_loss_kernel<<<nb + 1, THREADS, DYN_SMEM>>>(pred, tgt, M, out);
}